// round 13
// baseline (speedup 1.0000x reference)
#include <cuda_runtime.h>
#include <cuda_bf16.h>
#include <cstdint>
#include <mma.h>

using namespace nvcuda;

// ============================================================================
// DiseaseGraphEncoder: input proj -> 2x RGCN(basis) -> readout + node proj.
//
// R12: tcgen05 is unavailable (harness lowers via compute_103 base PTX, no 'a'
// features). Tensor path = WMMA bf16 (HMMA, base sm_80 feature) instead.
// Split-bf16 fp32-accuracy GEMM:  U@W ~= Uhi@Whi + Ulo@Whi + Uhi@Wlo.
//   layer:  agg = U(Nx320) @ W(320x64) + bself      (WMMA, W in smem)
//   output: node_emb = relu(h)(Nx64) @ Wnp(64x128)  (WMMA, same scheme)
// A-operands padded +128 rows so out-of-range warps load safely, never store.
// ============================================================================

#define NNODES 100000
#define NEDGES 1000000
#define SCAN_B 512
#define NSCANB ((NNODES + SCAN_B - 1) / SCAN_B)   // 196
#define NPAD   (NNODES + 128)

// -------------------- device scratch (no allocation allowed) ----------------
__device__ float g_h0  [(size_t)NNODES * 64];
__device__ __nv_bfloat16 g_Uhi[(size_t)NPAD * 320];
__device__ __nv_bfloat16 g_Ulo[(size_t)NPAD * 320];
__device__ __nv_bfloat16 g_Wthi[2][320 * 64];     // k-major [k][n]
__device__ __nv_bfloat16 g_Wtlo[2][320 * 64];
__device__ __nv_bfloat16 g_Wnphi[64 * 128];       // k-major [k][n]
__device__ __nv_bfloat16 g_Wnplo[64 * 128];
__device__ float g_brow[2][16 * 64];              // bself replicated 16 rows
__device__ float g_brownp[16 * 128];              // bnp replicated 16 rows
__device__ float g_aggA[(size_t)NNODES * 64];
__device__ float g_aggB[(size_t)NNODES * 64];
__device__ float g_psum[256 * 64];
__device__ float g_pmax[256 * 64];
__device__ int   g_deg   [NNODES];
__device__ int   g_rowptr[NNODES + 1];
__device__ int   g_cursor[NNODES];
__device__ int   g_bsum  [NSCANB];
__device__ int   g_epk   [NEDGES];                // src | (etype << 17)

__device__ __forceinline__ void split_store(__nv_bfloat16* hi, __nv_bfloat16* lo,
                                            size_t idx, float v) {
    __nv_bfloat16 h = __float2bfloat16(v);
    hi[idx] = h;
    lo[idx] = __float2bfloat16(v - __bfloat162float(h));
}

// ===================== CSR build =====================
__global__ void zero_deg_kernel()
{
    int i = blockIdx.x * blockDim.x + threadIdx.x;
    if (i < NNODES) g_deg[i] = 0;
}
__global__ void hist_kernel(const int* __restrict__ tgt)
{
    int e = blockIdx.x * blockDim.x + threadIdx.x;
    if (e < NEDGES) atomicAdd(&g_deg[tgt[e]], 1);
}
__global__ void scan1_kernel()
{
    __shared__ int s[SCAN_B];
    int i = blockIdx.x * SCAN_B + threadIdx.x;
    int v = (i < NNODES) ? g_deg[i] : 0;
    s[threadIdx.x] = v;
    __syncthreads();
    for (int off = 1; off < SCAN_B; off <<= 1) {
        int t = (threadIdx.x >= off) ? s[threadIdx.x - off] : 0;
        __syncthreads();
        s[threadIdx.x] += t;
        __syncthreads();
    }
    if (i < NNODES) g_rowptr[i] = s[threadIdx.x] - v;
    if (threadIdx.x == SCAN_B - 1) g_bsum[blockIdx.x] = s[threadIdx.x];
}
__global__ void scan2_kernel()
{
    __shared__ int s[256];
    int v = (threadIdx.x < NSCANB) ? g_bsum[threadIdx.x] : 0;
    s[threadIdx.x] = v;
    __syncthreads();
    for (int off = 1; off < 256; off <<= 1) {
        int t = (threadIdx.x >= off) ? s[threadIdx.x - off] : 0;
        __syncthreads();
        s[threadIdx.x] += t;
        __syncthreads();
    }
    if (threadIdx.x < NSCANB) g_bsum[threadIdx.x] = s[threadIdx.x] - v;
}
__global__ void scan3_kernel()
{
    int i = blockIdx.x * SCAN_B + threadIdx.x;
    if (i < NNODES) {
        int v = g_rowptr[i] + g_bsum[blockIdx.x];
        g_rowptr[i] = v;
        g_cursor[i] = v;
    }
    if (i == 0) g_rowptr[NNODES] = NEDGES;
}
__global__ void scatter_kernel(const int* __restrict__ src,
                               const int* __restrict__ tgt,
                               const int* __restrict__ et)
{
    int e = blockIdx.x * blockDim.x + threadIdx.x;
    if (e >= NEDGES) return;
    int pos = atomicAdd(&g_cursor[tgt[e]], 1);
    g_epk[pos] = src[e] | (et[e] << 17);
}

// -------------------- input projection: (N,15) @ (15,64) + b ----------------
__global__ void inproj_kernel(const float* __restrict__ nf,
                              const float* __restrict__ W,
                              const float* __restrict__ b)
{
    __shared__ float Ws[15 * 64];
    __shared__ float bs[64];
    __shared__ float nfs[4 * 15];
    int tid = threadIdx.x;
    for (int i = tid; i < 15 * 64; i += 256) Ws[i] = W[i];
    if (tid < 64) bs[tid] = b[tid];
    int n0 = blockIdx.x * 4;
    if (tid < 60) {
        int node = n0 + tid / 15;
        nfs[tid] = (node < NNODES) ? nf[(size_t)node * 15 + (tid % 15)] : 0.f;
    }
    __syncthreads();
    int l = tid >> 6, j = tid & 63;
    int node = n0 + l;
    if (node < NNODES) {
        float s = bs[j];
#pragma unroll
        for (int k = 0; k < 15; k++) s += nfs[l * 15 + k] * Ws[k * 64 + j];
        g_h0[(size_t)node * 64 + j] = s;
    }
}

// -------------------- W prep: split hi/lo bf16, k-major; bias tiles ---------
__global__ void prep_w_kernel(const float* __restrict__ bases0,
                              const float* __restrict__ Wself0,
                              const float* __restrict__ bself0,
                              const float* __restrict__ bases1,
                              const float* __restrict__ Wself1,
                              const float* __restrict__ bself1,
                              const float* __restrict__ Wnp,
                              const float* __restrict__ bnp)
{
    if (blockIdx.x < 2) {
        int layer = blockIdx.x;
        const float* bases = layer ? bases1 : bases0;
        const float* Wself = layer ? Wself1 : Wself0;
        const float* bself = layer ? bself1 : bself0;
        for (int i = threadIdx.x; i < 320 * 64; i += blockDim.x) {
            int k = i >> 6, n = i & 63;
            float w = (k < 256) ? bases[(k >> 6) * 4096 + (k & 63) * 64 + n]
                                : Wself[(k - 256) * 64 + n];
            split_store(g_Wthi[layer], g_Wtlo[layer], i, w);
        }
        for (int i = threadIdx.x; i < 16 * 64; i += blockDim.x)
            g_brow[layer][i] = bself[i & 63];
    } else {
        for (int i = threadIdx.x; i < 64 * 128; i += blockDim.x)
            split_store(g_Wnphi, g_Wnplo, i, Wnp[i]);
        for (int i = threadIdx.x; i < 16 * 128; i += blockDim.x)
            g_brownp[i] = bnp[i & 127];
    }
}

// ===================== gather: U[t] = sum_e c_b * h[src], warp/node =========
// Emits split-bf16 Uhi/Ulo (cols 0..255 basis-weighted sums, 256..319 self h).
__global__ void gather_kernel(const float* __restrict__ h,
                              const float* __restrict__ coeffs,  // (13,4)
                              int relu_in)
{
    __shared__ float csm[52];
    if (threadIdx.x < 52) csm[threadIdx.x] = coeffs[threadIdx.x];
    __syncthreads();
    int t    = (blockIdx.x * blockDim.x + threadIdx.x) >> 5;
    int lane = threadIdx.x & 31;
    if (t >= NNODES) return;
    int e   = g_rowptr[t];
    int end = g_rowptr[t + 1];

    float u00 = 0.f, u01 = 0.f, u10 = 0.f, u11 = 0.f;
    float u20 = 0.f, u21 = 0.f, u30 = 0.f, u31 = 0.f;

    if (e < end) {
        int pk = g_epk[e];
        while (true) {
            int s = pk & 0x1FFFF;
            int r = pk >> 17;
            float a = h[(size_t)s * 64 + lane];
            float b = h[(size_t)s * 64 + lane + 32];
            e++;
            bool more = (e < end);
            int pk_n = more ? g_epk[e] : 0;
            if (relu_in) { a = fmaxf(a, 0.f); b = fmaxf(b, 0.f); }
            float c0 = csm[r * 4 + 0], c1 = csm[r * 4 + 1];
            float c2 = csm[r * 4 + 2], c3 = csm[r * 4 + 3];
            u00 += c0 * a; u01 += c0 * b;
            u10 += c1 * a; u11 += c1 * b;
            u20 += c2 * a; u21 += c2 * b;
            u30 += c3 * a; u31 += c3 * b;
            if (!more) break;
            pk = pk_n;
        }
    }

    size_t base = (size_t)t * 320;
    split_store(g_Uhi, g_Ulo, base + lane +   0, u00);
    split_store(g_Uhi, g_Ulo, base + lane +  32, u01);
    split_store(g_Uhi, g_Ulo, base + lane +  64, u10);
    split_store(g_Uhi, g_Ulo, base + lane +  96, u11);
    split_store(g_Uhi, g_Ulo, base + lane + 128, u20);
    split_store(g_Uhi, g_Ulo, base + lane + 160, u21);
    split_store(g_Uhi, g_Ulo, base + lane + 192, u30);
    split_store(g_Uhi, g_Ulo, base + lane + 224, u31);
    float a = h[(size_t)t * 64 + lane];
    float b = h[(size_t)t * 64 + lane + 32];
    if (relu_in) { a = fmaxf(a, 0.f); b = fmaxf(b, 0.f); }
    split_store(g_Uhi, g_Ulo, base + lane + 256, a);
    split_store(g_Uhi, g_Ulo, base + lane + 288, b);
}

// ===================== WMMA layer GEMM ======================================
// agg(128x64/CTA) = [Uhi@Whi + Ulo@Whi + Uhi@Wlo] + bself.
// 8 warps; warp = 16 rows x 64 cols (4 n-tiles). W hi+lo staged in smem.
__global__ void __launch_bounds__(256)
layer_gemm_wmma(int layer, float* __restrict__ agg)
{
    extern __shared__ __nv_bfloat16 sW[];   // [0:20480) Whi, [20480:40960) Wlo
    int tid = threadIdx.x;
    {
        const uint4* sh = (const uint4*)g_Wthi[layer];
        const uint4* sl = (const uint4*)g_Wtlo[layer];
        uint4* dh = (uint4*)sW;
        uint4* dl = (uint4*)(sW + 320 * 64);
        for (int i = tid; i < 2560; i += 256) { dh[i] = sh[i]; dl[i] = sl[i]; }
    }
    __syncthreads();

    int w    = tid >> 5;
    int row0 = blockIdx.x * 128 + w * 16;

    wmma::fragment<wmma::accumulator, 16, 16, 16, float> acc[4];
#pragma unroll
    for (int n = 0; n < 4; n++)
        wmma::load_matrix_sync(acc[n], g_brow[layer] + n * 16, 64, wmma::mem_row_major);

    const __nv_bfloat16* Ah = g_Uhi + (size_t)row0 * 320;
    const __nv_bfloat16* Al = g_Ulo + (size_t)row0 * 320;
    wmma::fragment<wmma::matrix_a, 16, 16, 16, __nv_bfloat16, wmma::row_major> a_hi, a_lo;
    wmma::fragment<wmma::matrix_b, 16, 16, 16, __nv_bfloat16, wmma::row_major> b;

    for (int k0 = 0; k0 < 320; k0 += 16) {
        wmma::load_matrix_sync(a_hi, Ah + k0, 320);
        wmma::load_matrix_sync(a_lo, Al + k0, 320);
#pragma unroll
        for (int n = 0; n < 4; n++) {
            wmma::load_matrix_sync(b, sW + k0 * 64 + n * 16, 64);
            wmma::mma_sync(acc[n], a_hi, b, acc[n]);
            wmma::mma_sync(acc[n], a_lo, b, acc[n]);
            wmma::load_matrix_sync(b, sW + 320 * 64 + k0 * 64 + n * 16, 64);
            wmma::mma_sync(acc[n], a_hi, b, acc[n]);
        }
    }

    if (row0 < NNODES) {
        float* dst = agg + (size_t)row0 * 64;
#pragma unroll
        for (int n = 0; n < 4; n++)
            wmma::store_matrix_sync(dst + n * 16, acc[n], 64, wmma::mem_row_major);
    }
}

// -------------------- split relu(h) -> bf16 hi/lo (reuses U buffers) --------
__global__ void split_h_kernel(const float* __restrict__ h)
{
    int i = blockIdx.x * blockDim.x + threadIdx.x;
    if (i < NNODES * 64) {
        float v = fmaxf(h[i], 0.f);
        split_store(g_Uhi, g_Ulo, (size_t)i, v);
    }
}

// ===================== WMMA output GEMM =====================================
// node_emb(128x128/CTA) = [Hhi@Whi + Hlo@Whi + Hhi@Wlo] + bnp. K=64.
__global__ void __launch_bounds__(256)
gemm_out_wmma(float* __restrict__ C)
{
    extern __shared__ __nv_bfloat16 sW[];   // [0:8192) Whi, [8192:16384) Wlo
    int tid = threadIdx.x;
    {
        const uint4* sh = (const uint4*)g_Wnphi;
        const uint4* sl = (const uint4*)g_Wnplo;
        uint4* dh = (uint4*)sW;
        uint4* dl = (uint4*)(sW + 64 * 128);
        for (int i = tid; i < 1024; i += 256) { dh[i] = sh[i]; dl[i] = sl[i]; }
    }
    __syncthreads();

    int w    = tid >> 5;
    int row0 = blockIdx.x * 128 + w * 16;

    wmma::fragment<wmma::accumulator, 16, 16, 16, float> acc[8];
#pragma unroll
    for (int n = 0; n < 8; n++)
        wmma::load_matrix_sync(acc[n], g_brownp + n * 16, 128, wmma::mem_row_major);

    const __nv_bfloat16* Ah = g_Uhi + (size_t)row0 * 64;
    const __nv_bfloat16* Al = g_Ulo + (size_t)row0 * 64;
    wmma::fragment<wmma::matrix_a, 16, 16, 16, __nv_bfloat16, wmma::row_major> a_hi, a_lo;
    wmma::fragment<wmma::matrix_b, 16, 16, 16, __nv_bfloat16, wmma::row_major> b;

    for (int k0 = 0; k0 < 64; k0 += 16) {
        wmma::load_matrix_sync(a_hi, Ah + k0, 64);
        wmma::load_matrix_sync(a_lo, Al + k0, 64);
#pragma unroll
        for (int n = 0; n < 8; n++) {
            wmma::load_matrix_sync(b, sW + k0 * 128 + n * 16, 128);
            wmma::mma_sync(acc[n], a_hi, b, acc[n]);
            wmma::mma_sync(acc[n], a_lo, b, acc[n]);
            wmma::load_matrix_sync(b, sW + 64 * 128 + k0 * 128 + n * 16, 128);
            wmma::mma_sync(acc[n], a_hi, b, acc[n]);
        }
    }

    if (row0 < NNODES) {
        float* dst = C + (size_t)row0 * 128;
#pragma unroll
        for (int n = 0; n < 8; n++)
            wmma::store_matrix_sync(dst + n * 16, acc[n], 128, wmma::mem_row_major);
    }
}

// -------------------- pooling: per-block partial sum/max of relu(h) ---------
__global__ void pool_partial_kernel(const float* __restrict__ h)
{
    __shared__ float ss[256], sm[256];
    int tid = threadIdx.x;
    int col = tid & 63, r = tid >> 6;
    float s = 0.f, mx = 0.f;
    for (int node = blockIdx.x * 4 + r; node < NNODES; node += gridDim.x * 4) {
        float v = fmaxf(h[(size_t)node * 64 + col], 0.f);
        s += v; mx = fmaxf(mx, v);
    }
    ss[tid] = s; sm[tid] = mx;
    __syncthreads();
    if (tid < 128) { ss[tid] += ss[tid + 128]; sm[tid] = fmaxf(sm[tid], sm[tid + 128]); }
    __syncthreads();
    if (tid < 64) {
        g_psum[blockIdx.x * 64 + col] = ss[tid] + ss[tid + 64];
        g_pmax[blockIdx.x * 64 + col] = fmaxf(sm[tid], sm[tid + 64]);
    }
}

// -------------------- final reduce + readout MLP (1 block, 128 thr) ---------
__global__ void pool_final_kernel(const float* __restrict__ Wr1,
                                  const float* __restrict__ br1,
                                  const float* __restrict__ Wr2,
                                  const float* __restrict__ br2,
                                  float* __restrict__ out)
{
    __shared__ float g[128], t[64];
    int tid = threadIdx.x;
    if (tid < 64) {
        float s = 0.f, mx = 0.f;
        for (int b = 0; b < 256; b++) {
            s += g_psum[b * 64 + tid];
            mx = fmaxf(mx, g_pmax[b * 64 + tid]);
        }
        g[tid]      = s / (float)NNODES;
        g[64 + tid] = mx;
    }
    __syncthreads();
    if (tid < 64) {
        float acc = br1[tid];
#pragma unroll 8
        for (int k = 0; k < 128; k++) acc += g[k] * Wr1[k * 64 + tid];
        t[tid] = fmaxf(acc, 0.f);
    }
    __syncthreads();
    {
        float acc = br2[tid];
#pragma unroll 8
        for (int i = 0; i < 64; i++) acc += t[i] * Wr2[i * 128 + tid];
        out[tid] = acc;
    }
}

// ============================================================================
extern "C" void kernel_launch(void* const* d_in, const int* in_sizes, int n_in,
                              void* d_out, int out_size)
{
    const float* nf     = (const float*)d_in[0];
    const int*   eidx   = (const int*)  d_in[1];
    const int*   etype  = (const int*)  d_in[2];
    const float* W_in   = (const float*)d_in[3];
    const float* b_in   = (const float*)d_in[4];
    const float* Wself0 = (const float*)d_in[5];
    const float* bself0 = (const float*)d_in[6];
    const float* bases0 = (const float*)d_in[7];
    const float* coef0  = (const float*)d_in[8];
    const float* Wself1 = (const float*)d_in[9];
    const float* bself1 = (const float*)d_in[10];
    const float* bases1 = (const float*)d_in[11];
    const float* coef1  = (const float*)d_in[12];
    const float* Wr1    = (const float*)d_in[13];
    const float* br1    = (const float*)d_in[14];
    const float* Wr2    = (const float*)d_in[15];
    const float* br2    = (const float*)d_in[16];
    const float* Wnp    = (const float*)d_in[17];
    const float* bnp    = (const float*)d_in[18];
    float* out = (float*)d_out;

    const int* src = eidx;
    const int* tgt = eidx + NEDGES;

    float *p_h0, *p_aggA, *p_aggB;
    cudaGetSymbolAddress((void**)&p_h0,   g_h0);
    cudaGetSymbolAddress((void**)&p_aggA, g_aggA);
    cudaGetSymbolAddress((void**)&p_aggB, g_aggB);

    const int smem_layer = 2 * 320 * 64 * (int)sizeof(__nv_bfloat16);  // 81920
    const int smem_out   = 2 * 64 * 128 * (int)sizeof(__nv_bfloat16);  // 32768
    cudaFuncSetAttribute(layer_gemm_wmma,
                         cudaFuncAttributeMaxDynamicSharedMemorySize, smem_layer);

    int wtiles = (NNODES + 127) / 128;   // 782

    // 1. input projection + weight prep
    inproj_kernel<<<(NNODES + 3) / 4, 256>>>(nf, W_in, b_in);
    prep_w_kernel<<<3, 256>>>(bases0, Wself0, bself0, bases1, Wself1, bself1,
                              Wnp, bnp);

    // 2. CSR build (once, shared by both layers)
    zero_deg_kernel<<<(NNODES + 255) / 256, 256>>>();
    hist_kernel<<<(NEDGES + 255) / 256, 256>>>(tgt);
    scan1_kernel<<<NSCANB, SCAN_B>>>();
    scan2_kernel<<<1, 256>>>();
    scan3_kernel<<<NSCANB, SCAN_B>>>();
    scatter_kernel<<<(NEDGES + 255) / 256, 256>>>(src, tgt, etype);

    // 3. layer 0: gather split-bf16 U from h0, WMMA transform
    gather_kernel<<<(NNODES * 32 + 255) / 256, 256>>>(p_h0, coef0, /*relu=*/0);
    layer_gemm_wmma<<<wtiles, 256, smem_layer>>>(0, p_aggA);

    // 4. layer 1: gather from relu(aggA), WMMA transform
    gather_kernel<<<(NNODES * 32 + 255) / 256, 256>>>(p_aggA, coef1, /*relu=*/1);
    layer_gemm_wmma<<<wtiles, 256, smem_layer>>>(1, p_aggB);

    // 5. node embeddings: split relu(aggB), WMMA -> out[128:]
    split_h_kernel<<<(NNODES * 64 + 255) / 256, 256>>>(p_aggB);
    gemm_out_wmma<<<wtiles, 256, smem_out>>>(out + 128);

    // 6. graph embedding: mean+max pool of relu(aggB) -> MLP -> out[0:128]
    pool_partial_kernel<<<256, 256>>>(p_aggB);
    pool_final_kernel<<<1, 128>>>(Wr1, br1, Wr2, br2, out);
}

// round 14
// speedup vs baseline: 1.5634x; 1.5634x over previous
#include <cuda_runtime.h>
#include <cuda_bf16.h>
#include <cstdint>
#include <mma.h>

using namespace nvcuda;

// ============================================================================
// DiseaseGraphEncoder: input proj -> 2x RGCN(basis) -> readout + node proj.
//
// R14: WMMA bf16 split GEMMs with SMEM-staged operands (R13 regressed because
// load_matrix_sync pulled A fragments straight from global, uncoalesced).
//   U@W ~= Uhi@Whi + Ulo@Whi + Uhi@Wlo   (split-bf16, fp32 accumulate)
// layer GEMM: W(hi+lo) resident in smem (ld=72, conflict-free ldmatrix);
// A streamed in 64-wide K chunks via cp.async, double-buffered.
// ============================================================================

#define NNODES 100000
#define NEDGES 1000000
#define SCAN_B 512
#define NSCANB ((NNODES + SCAN_B - 1) / SCAN_B)   // 196
#define NPAD   (NNODES + 128)

// -------------------- device scratch (no allocation allowed) ----------------
__device__ __align__(16) float g_h0  [(size_t)NNODES * 64];
__device__ __align__(16) __nv_bfloat16 g_Uhi[(size_t)NPAD * 320];
__device__ __align__(16) __nv_bfloat16 g_Ulo[(size_t)NPAD * 320];
__device__ __align__(16) __nv_bfloat16 g_Wthi[2][320 * 64];   // k-major [k][n]
__device__ __align__(16) __nv_bfloat16 g_Wtlo[2][320 * 64];
__device__ __align__(16) __nv_bfloat16 g_Wnphi[64 * 128];     // k-major [k][n]
__device__ __align__(16) __nv_bfloat16 g_Wnplo[64 * 128];
__device__ float g_brow[2][16 * 64];              // bself replicated 16 rows
__device__ float g_brownp[16 * 128];              // bnp replicated 16 rows
__device__ float g_aggA[(size_t)NNODES * 64];
__device__ float g_aggB[(size_t)NNODES * 64];
__device__ float g_psum[256 * 64];
__device__ float g_pmax[256 * 64];
__device__ int   g_deg   [NNODES];
__device__ int   g_rowptr[NNODES + 1];
__device__ int   g_cursor[NNODES];
__device__ int   g_bsum  [NSCANB];
__device__ int   g_epk   [NEDGES];                // src | (etype << 17)

__device__ __forceinline__ void split_store(__nv_bfloat16* hi, __nv_bfloat16* lo,
                                            size_t idx, float v) {
    __nv_bfloat16 h = __float2bfloat16(v);
    hi[idx] = h;
    lo[idx] = __float2bfloat16(v - __bfloat162float(h));
}

__device__ __forceinline__ void cp_async16(uint32_t dst, const void* src) {
    asm volatile("cp.async.cg.shared.global [%0], [%1], 16;" :: "r"(dst), "l"(src));
}
#define CP_COMMIT() asm volatile("cp.async.commit_group;" ::: "memory")
#define CP_WAIT(N)  asm volatile("cp.async.wait_group %0;" :: "n"(N) : "memory")

// ===================== CSR build =====================
__global__ void zero_deg_kernel()
{
    int i = blockIdx.x * blockDim.x + threadIdx.x;
    if (i < NNODES) g_deg[i] = 0;
}
__global__ void hist_kernel(const int* __restrict__ tgt)
{
    int e = blockIdx.x * blockDim.x + threadIdx.x;
    if (e < NEDGES) atomicAdd(&g_deg[tgt[e]], 1);
}
__global__ void scan1_kernel()
{
    __shared__ int s[SCAN_B];
    int i = blockIdx.x * SCAN_B + threadIdx.x;
    int v = (i < NNODES) ? g_deg[i] : 0;
    s[threadIdx.x] = v;
    __syncthreads();
    for (int off = 1; off < SCAN_B; off <<= 1) {
        int t = (threadIdx.x >= off) ? s[threadIdx.x - off] : 0;
        __syncthreads();
        s[threadIdx.x] += t;
        __syncthreads();
    }
    if (i < NNODES) g_rowptr[i] = s[threadIdx.x] - v;
    if (threadIdx.x == SCAN_B - 1) g_bsum[blockIdx.x] = s[threadIdx.x];
}
__global__ void scan2_kernel()
{
    __shared__ int s[256];
    int v = (threadIdx.x < NSCANB) ? g_bsum[threadIdx.x] : 0;
    s[threadIdx.x] = v;
    __syncthreads();
    for (int off = 1; off < 256; off <<= 1) {
        int t = (threadIdx.x >= off) ? s[threadIdx.x - off] : 0;
        __syncthreads();
        s[threadIdx.x] += t;
        __syncthreads();
    }
    if (threadIdx.x < NSCANB) g_bsum[threadIdx.x] = s[threadIdx.x] - v;
}
__global__ void scan3_kernel()
{
    int i = blockIdx.x * SCAN_B + threadIdx.x;
    if (i < NNODES) {
        int v = g_rowptr[i] + g_bsum[blockIdx.x];
        g_rowptr[i] = v;
        g_cursor[i] = v;
    }
    if (i == 0) g_rowptr[NNODES] = NEDGES;
}
__global__ void scatter_kernel(const int* __restrict__ src,
                               const int* __restrict__ tgt,
                               const int* __restrict__ et)
{
    int e = blockIdx.x * blockDim.x + threadIdx.x;
    if (e >= NEDGES) return;
    int pos = atomicAdd(&g_cursor[tgt[e]], 1);
    g_epk[pos] = src[e] | (et[e] << 17);
}

// -------------------- input projection: (N,15) @ (15,64) + b ----------------
__global__ void inproj_kernel(const float* __restrict__ nf,
                              const float* __restrict__ W,
                              const float* __restrict__ b)
{
    __shared__ float Ws[15 * 64];
    __shared__ float bs[64];
    __shared__ float nfs[4 * 15];
    int tid = threadIdx.x;
    for (int i = tid; i < 15 * 64; i += 256) Ws[i] = W[i];
    if (tid < 64) bs[tid] = b[tid];
    int n0 = blockIdx.x * 4;
    if (tid < 60) {
        int node = n0 + tid / 15;
        nfs[tid] = (node < NNODES) ? nf[(size_t)node * 15 + (tid % 15)] : 0.f;
    }
    __syncthreads();
    int l = tid >> 6, j = tid & 63;
    int node = n0 + l;
    if (node < NNODES) {
        float s = bs[j];
#pragma unroll
        for (int k = 0; k < 15; k++) s += nfs[l * 15 + k] * Ws[k * 64 + j];
        g_h0[(size_t)node * 64 + j] = s;
    }
}

// -------------------- W prep: split hi/lo bf16, k-major; bias tiles ---------
__global__ void prep_w_kernel(const float* __restrict__ bases0,
                              const float* __restrict__ Wself0,
                              const float* __restrict__ bself0,
                              const float* __restrict__ bases1,
                              const float* __restrict__ Wself1,
                              const float* __restrict__ bself1,
                              const float* __restrict__ Wnp,
                              const float* __restrict__ bnp)
{
    if (blockIdx.x < 2) {
        int layer = blockIdx.x;
        const float* bases = layer ? bases1 : bases0;
        const float* Wself = layer ? Wself1 : Wself0;
        const float* bself = layer ? bself1 : bself0;
        for (int i = threadIdx.x; i < 320 * 64; i += blockDim.x) {
            int k = i >> 6, n = i & 63;
            float w = (k < 256) ? bases[(k >> 6) * 4096 + (k & 63) * 64 + n]
                                : Wself[(k - 256) * 64 + n];
            split_store(g_Wthi[layer], g_Wtlo[layer], i, w);
        }
        for (int i = threadIdx.x; i < 16 * 64; i += blockDim.x)
            g_brow[layer][i] = bself[i & 63];
    } else {
        for (int i = threadIdx.x; i < 64 * 128; i += blockDim.x)
            split_store(g_Wnphi, g_Wnplo, i, Wnp[i]);
        for (int i = threadIdx.x; i < 16 * 128; i += blockDim.x)
            g_brownp[i] = bnp[i & 127];
    }
}

// ===================== gather: U[t] = sum_e c_b * h[src], warp/node =========
__global__ void gather_kernel(const float* __restrict__ h,
                              const float* __restrict__ coeffs,  // (13,4)
                              int relu_in)
{
    __shared__ float csm[52];
    if (threadIdx.x < 52) csm[threadIdx.x] = coeffs[threadIdx.x];
    __syncthreads();
    int t    = (blockIdx.x * blockDim.x + threadIdx.x) >> 5;
    int lane = threadIdx.x & 31;
    if (t >= NNODES) return;
    int e   = g_rowptr[t];
    int end = g_rowptr[t + 1];

    float u00 = 0.f, u01 = 0.f, u10 = 0.f, u11 = 0.f;
    float u20 = 0.f, u21 = 0.f, u30 = 0.f, u31 = 0.f;

    if (e < end) {
        int pk = g_epk[e];
        while (true) {
            int s = pk & 0x1FFFF;
            int r = pk >> 17;
            float a = h[(size_t)s * 64 + lane];
            float b = h[(size_t)s * 64 + lane + 32];
            e++;
            bool more = (e < end);
            int pk_n = more ? g_epk[e] : 0;
            if (relu_in) { a = fmaxf(a, 0.f); b = fmaxf(b, 0.f); }
            float c0 = csm[r * 4 + 0], c1 = csm[r * 4 + 1];
            float c2 = csm[r * 4 + 2], c3 = csm[r * 4 + 3];
            u00 += c0 * a; u01 += c0 * b;
            u10 += c1 * a; u11 += c1 * b;
            u20 += c2 * a; u21 += c2 * b;
            u30 += c3 * a; u31 += c3 * b;
            if (!more) break;
            pk = pk_n;
        }
    }

    size_t base = (size_t)t * 320;
    split_store(g_Uhi, g_Ulo, base + lane +   0, u00);
    split_store(g_Uhi, g_Ulo, base + lane +  32, u01);
    split_store(g_Uhi, g_Ulo, base + lane +  64, u10);
    split_store(g_Uhi, g_Ulo, base + lane +  96, u11);
    split_store(g_Uhi, g_Ulo, base + lane + 128, u20);
    split_store(g_Uhi, g_Ulo, base + lane + 160, u21);
    split_store(g_Uhi, g_Ulo, base + lane + 192, u30);
    split_store(g_Uhi, g_Ulo, base + lane + 224, u31);
    float a = h[(size_t)t * 64 + lane];
    float b = h[(size_t)t * 64 + lane + 32];
    if (relu_in) { a = fmaxf(a, 0.f); b = fmaxf(b, 0.f); }
    split_store(g_Uhi, g_Ulo, base + lane + 256, a);
    split_store(g_Uhi, g_Ulo, base + lane + 288, b);
}

// ===================== WMMA layer GEMM (smem-staged, cp.async) ==============
// agg(128x64/CTA) = [Uhi@Whi + Ulo@Whi + Uhi@Wlo] + bself.
// smem (bf16 elems): Whi[320*72] @0, Wlo @23040, A bufs @46080 (2 x 18432:
// hi 128*72 then lo 128*72). ld=72 (144B rows) -> ldmatrix conflict-free.
#define LG_SMEM_ELEMS 82944   // *2B = 165888 bytes
#define LG_WLO 23040
#define LG_A0  46080
#define LG_ABUF 18432
#define LG_ALO 9216

__device__ __forceinline__ void lg_load_chunk(uint32_t sA, int m0, int chunk)
{
    int tid = threadIdx.x;
#pragma unroll
    for (int i = 0; i < 8; i++) {
        int idx  = tid + i * 256;          // 0..2047
        int half = idx >> 10;              // 0=hi, 1=lo
        int j    = idx & 1023;
        int row  = j >> 3, c8 = j & 7;
        const __nv_bfloat16* g = (half ? g_Ulo : g_Uhi)
            + (size_t)(m0 + row) * 320 + chunk * 64 + c8 * 8;
        uint32_t d = sA + (uint32_t)(half * LG_ALO + row * 72 + c8 * 8) * 2;
        cp_async16(d, g);
    }
}

__global__ void __launch_bounds__(256)
layer_gemm_wmma(int layer, float* __restrict__ agg)
{
    extern __shared__ __align__(16) __nv_bfloat16 sm[];
    int tid = threadIdx.x;
    int m0  = blockIdx.x * 128;
    uint32_t sbase = (uint32_t)__cvta_generic_to_shared(sm);

    // stage W hi+lo (ld 72), coalesced uint4
    {
        const uint4* sh = (const uint4*)g_Wthi[layer];
        const uint4* sl = (const uint4*)g_Wtlo[layer];
        for (int i = tid; i < 2560; i += 256) {
            int row = i >> 3, c8 = i & 7;
            int d = row * 72 + c8 * 8;
            *(uint4*)(sm + d)          = sh[i];
            *(uint4*)(sm + LG_WLO + d) = sl[i];
        }
    }

    // prologue: chunk 0 -> buf 0
    lg_load_chunk(sbase + LG_A0 * 2, m0, 0);
    CP_COMMIT();

    int w      = tid >> 5;
    int warp_r = w >> 1;            // 0..3 -> 32 rows each
    int warp_c = w & 1;             // 0..1 -> 32 cols each
    int rb = warp_r * 32;
    int cb = warp_c * 32;

    wmma::fragment<wmma::accumulator, 16, 16, 16, float> acc[2][2];
#pragma unroll
    for (int mm = 0; mm < 2; mm++)
#pragma unroll
        for (int nn = 0; nn < 2; nn++)
            wmma::load_matrix_sync(acc[mm][nn], g_brow[layer] + cb + nn * 16,
                                   64, wmma::mem_row_major);

    wmma::fragment<wmma::matrix_a, 16, 16, 16, __nv_bfloat16, wmma::row_major> a_hi[2], a_lo[2];
    wmma::fragment<wmma::matrix_b, 16, 16, 16, __nv_bfloat16, wmma::row_major> b_hi, b_lo;

    for (int c = 0; c < 5; c++) {
        int buf = c & 1;
        if (c + 1 < 5) {
            lg_load_chunk(sbase + (LG_A0 + (buf ^ 1) * LG_ABUF) * 2, m0, c + 1);
            CP_COMMIT();
            CP_WAIT(1);
        } else {
            CP_WAIT(0);
        }
        __syncthreads();

        const __nv_bfloat16* Ah = sm + LG_A0 + buf * LG_ABUF;
        const __nv_bfloat16* Al = Ah + LG_ALO;
#pragma unroll
        for (int kk = 0; kk < 4; kk++) {
            int k0 = c * 64 + kk * 16;
#pragma unroll
            for (int mm = 0; mm < 2; mm++) {
                wmma::load_matrix_sync(a_hi[mm], Ah + (rb + mm * 16) * 72 + kk * 16, 72);
                wmma::load_matrix_sync(a_lo[mm], Al + (rb + mm * 16) * 72 + kk * 16, 72);
            }
#pragma unroll
            for (int nn = 0; nn < 2; nn++) {
                wmma::load_matrix_sync(b_hi, sm + k0 * 72 + cb + nn * 16, 72);
                wmma::load_matrix_sync(b_lo, sm + LG_WLO + k0 * 72 + cb + nn * 16, 72);
#pragma unroll
                for (int mm = 0; mm < 2; mm++) {
                    wmma::mma_sync(acc[mm][nn], a_hi[mm], b_hi, acc[mm][nn]);
                    wmma::mma_sync(acc[mm][nn], a_lo[mm], b_hi, acc[mm][nn]);
                    wmma::mma_sync(acc[mm][nn], a_hi[mm], b_lo, acc[mm][nn]);
                }
            }
        }
        __syncthreads();
    }

#pragma unroll
    for (int mm = 0; mm < 2; mm++) {
        int row0 = m0 + rb + mm * 16;
        if (row0 < NNODES) {
            float* dst = agg + (size_t)row0 * 64 + cb;
#pragma unroll
            for (int nn = 0; nn < 2; nn++)
                wmma::store_matrix_sync(dst + nn * 16, acc[mm][nn], 64,
                                        wmma::mem_row_major);
        }
    }
}

// -------------------- split relu(h) -> bf16 hi/lo (reuses U buffers) --------
__global__ void split_h_kernel(const float* __restrict__ h)
{
    int i = blockIdx.x * blockDim.x + threadIdx.x;
    if (i < NNODES * 64) {
        float v = fmaxf(h[i], 0.f);
        split_store(g_Uhi, g_Ulo, (size_t)i, v);
    }
}

// ===================== WMMA output GEMM (smem-staged) =======================
// node_emb(128x128/CTA) = [Hhi@Whi + Hlo@Whi + Hhi@Wlo] + bnp. K=64.
// smem elems: Whi[64*136] @0, Wlo @8704, Ahi[128*72] @17408, Alo @26624.
#define GO_SMEM_ELEMS 35840   // *2B = 71680 bytes
#define GO_WLO 8704
#define GO_AHI 17408
#define GO_ALO 26624

__global__ void __launch_bounds__(256)
gemm_out_wmma(float* __restrict__ C)
{
    extern __shared__ __align__(16) __nv_bfloat16 sm[];
    int tid = threadIdx.x;
    int m0  = blockIdx.x * 128;

    {   // W hi+lo (ld 136)
        const uint4* sh = (const uint4*)g_Wnphi;
        const uint4* sl = (const uint4*)g_Wnplo;
        for (int i = tid; i < 1024; i += 256) {
            int row = i >> 4, c8 = i & 15;
            int d = row * 136 + c8 * 8;
            *(uint4*)(sm + d)          = sh[i];
            *(uint4*)(sm + GO_WLO + d) = sl[i];
        }
    }
    {   // A hi+lo (ld 72)
        for (int i = tid; i < 2048; i += 256) {
            int half = i >> 10;
            int j    = i & 1023;
            int row  = j >> 3, c8 = j & 7;
            const uint4* g = (const uint4*)((half ? g_Ulo : g_Uhi)
                                            + (size_t)(m0 + row) * 64) + c8;
            *(uint4*)(sm + (half ? GO_ALO : GO_AHI) + row * 72 + c8 * 8) = *g;
        }
    }
    __syncthreads();

    int w  = tid >> 5;
    int rb = w * 16;

    wmma::fragment<wmma::accumulator, 16, 16, 16, float> acc[8];
#pragma unroll
    for (int nn = 0; nn < 8; nn++)
        wmma::load_matrix_sync(acc[nn], g_brownp + nn * 16, 128, wmma::mem_row_major);

    wmma::fragment<wmma::matrix_a, 16, 16, 16, __nv_bfloat16, wmma::row_major> a_hi, a_lo;
    wmma::fragment<wmma::matrix_b, 16, 16, 16, __nv_bfloat16, wmma::row_major> b_hi, b_lo;

#pragma unroll
    for (int kk = 0; kk < 4; kk++) {
        wmma::load_matrix_sync(a_hi, sm + GO_AHI + rb * 72 + kk * 16, 72);
        wmma::load_matrix_sync(a_lo, sm + GO_ALO + rb * 72 + kk * 16, 72);
#pragma unroll
        for (int nn = 0; nn < 8; nn++) {
            wmma::load_matrix_sync(b_hi, sm + kk * 16 * 136 + nn * 16, 136);
            wmma::load_matrix_sync(b_lo, sm + GO_WLO + kk * 16 * 136 + nn * 16, 136);
            wmma::mma_sync(acc[nn], a_hi, b_hi, acc[nn]);
            wmma::mma_sync(acc[nn], a_lo, b_hi, acc[nn]);
            wmma::mma_sync(acc[nn], a_hi, b_lo, acc[nn]);
        }
    }

    int row0 = m0 + rb;
    if (row0 < NNODES) {
        float* dst = C + (size_t)row0 * 128;
#pragma unroll
        for (int nn = 0; nn < 8; nn++)
            wmma::store_matrix_sync(dst + nn * 16, acc[nn], 128, wmma::mem_row_major);
    }
}

// -------------------- pooling: per-block partial sum/max of relu(h) ---------
__global__ void pool_partial_kernel(const float* __restrict__ h)
{
    __shared__ float ss[256], sm[256];
    int tid = threadIdx.x;
    int col = tid & 63, r = tid >> 6;
    float s = 0.f, mx = 0.f;
    for (int node = blockIdx.x * 4 + r; node < NNODES; node += gridDim.x * 4) {
        float v = fmaxf(h[(size_t)node * 64 + col], 0.f);
        s += v; mx = fmaxf(mx, v);
    }
    ss[tid] = s; sm[tid] = mx;
    __syncthreads();
    if (tid < 128) { ss[tid] += ss[tid + 128]; sm[tid] = fmaxf(sm[tid], sm[tid + 128]); }
    __syncthreads();
    if (tid < 64) {
        g_psum[blockIdx.x * 64 + col] = ss[tid] + ss[tid + 64];
        g_pmax[blockIdx.x * 64 + col] = fmaxf(sm[tid], sm[tid + 64]);
    }
}

// -------------------- final reduce + readout MLP (1 block, 128 thr) ---------
__global__ void pool_final_kernel(const float* __restrict__ Wr1,
                                  const float* __restrict__ br1,
                                  const float* __restrict__ Wr2,
                                  const float* __restrict__ br2,
                                  float* __restrict__ out)
{
    __shared__ float g[128], t[64];
    int tid = threadIdx.x;
    if (tid < 64) {
        float s = 0.f, mx = 0.f;
        for (int b = 0; b < 256; b++) {
            s += g_psum[b * 64 + tid];
            mx = fmaxf(mx, g_pmax[b * 64 + tid]);
        }
        g[tid]      = s / (float)NNODES;
        g[64 + tid] = mx;
    }
    __syncthreads();
    if (tid < 64) {
        float acc = br1[tid];
#pragma unroll 8
        for (int k = 0; k < 128; k++) acc += g[k] * Wr1[k * 64 + tid];
        t[tid] = fmaxf(acc, 0.f);
    }
    __syncthreads();
    {
        float acc = br2[tid];
#pragma unroll 8
        for (int i = 0; i < 64; i++) acc += t[i] * Wr2[i * 128 + tid];
        out[tid] = acc;
    }
}

// ============================================================================
extern "C" void kernel_launch(void* const* d_in, const int* in_sizes, int n_in,
                              void* d_out, int out_size)
{
    const float* nf     = (const float*)d_in[0];
    const int*   eidx   = (const int*)  d_in[1];
    const int*   etype  = (const int*)  d_in[2];
    const float* W_in   = (const float*)d_in[3];
    const float* b_in   = (const float*)d_in[4];
    const float* Wself0 = (const float*)d_in[5];
    const float* bself0 = (const float*)d_in[6];
    const float* bases0 = (const float*)d_in[7];
    const float* coef0  = (const float*)d_in[8];
    const float* Wself1 = (const float*)d_in[9];
    const float* bself1 = (const float*)d_in[10];
    const float* bases1 = (const float*)d_in[11];
    const float* coef1  = (const float*)d_in[12];
    const float* Wr1    = (const float*)d_in[13];
    const float* br1    = (const float*)d_in[14];
    const float* Wr2    = (const float*)d_in[15];
    const float* br2    = (const float*)d_in[16];
    const float* Wnp    = (const float*)d_in[17];
    const float* bnp    = (const float*)d_in[18];
    float* out = (float*)d_out;

    const int* src = eidx;
    const int* tgt = eidx + NEDGES;

    float *p_h0, *p_aggA, *p_aggB;
    cudaGetSymbolAddress((void**)&p_h0,   g_h0);
    cudaGetSymbolAddress((void**)&p_aggA, g_aggA);
    cudaGetSymbolAddress((void**)&p_aggB, g_aggB);

    const int smem_layer = LG_SMEM_ELEMS * 2;   // 165888
    const int smem_out   = GO_SMEM_ELEMS * 2;   // 71680
    cudaFuncSetAttribute(layer_gemm_wmma,
                         cudaFuncAttributeMaxDynamicSharedMemorySize, smem_layer);
    cudaFuncSetAttribute(gemm_out_wmma,
                         cudaFuncAttributeMaxDynamicSharedMemorySize, smem_out);

    int wtiles = (NNODES + 127) / 128;   // 782

    // 1. input projection + weight prep
    inproj_kernel<<<(NNODES + 3) / 4, 256>>>(nf, W_in, b_in);
    prep_w_kernel<<<3, 256>>>(bases0, Wself0, bself0, bases1, Wself1, bself1,
                              Wnp, bnp);

    // 2. CSR build (once, shared by both layers)
    zero_deg_kernel<<<(NNODES + 255) / 256, 256>>>();
    hist_kernel<<<(NEDGES + 255) / 256, 256>>>(tgt);
    scan1_kernel<<<NSCANB, SCAN_B>>>();
    scan2_kernel<<<1, 256>>>();
    scan3_kernel<<<NSCANB, SCAN_B>>>();
    scatter_kernel<<<(NEDGES + 255) / 256, 256>>>(src, tgt, etype);

    // 3. layer 0: gather split-bf16 U from h0, WMMA transform
    gather_kernel<<<(NNODES * 32 + 255) / 256, 256>>>(p_h0, coef0, /*relu=*/0);
    layer_gemm_wmma<<<wtiles, 256, smem_layer>>>(0, p_aggA);

    // 4. layer 1: gather from relu(aggA), WMMA transform
    gather_kernel<<<(NNODES * 32 + 255) / 256, 256>>>(p_aggA, coef1, /*relu=*/1);
    layer_gemm_wmma<<<wtiles, 256, smem_layer>>>(1, p_aggB);

    // 5. node embeddings: split relu(aggB), WMMA -> out[128:]
    split_h_kernel<<<(NNODES * 64 + 255) / 256, 256>>>(p_aggB);
    gemm_out_wmma<<<wtiles, 256, smem_out>>>(out + 128);

    // 6. graph embedding: mean+max pool of relu(aggB) -> MLP -> out[0:128]
    pool_partial_kernel<<<256, 256>>>(p_aggB);
    pool_final_kernel<<<1, 128>>>(Wr1, br1, Wr2, br2, out);
}